// round 2
// baseline (speedup 1.0000x reference)
#include <cuda_runtime.h>
#include <cuda_bf16.h>

// Problem constants
#define BB 4
#define SS 1024
#define DD 2048

// Scratch (allocation-free rule: __device__ globals)
__device__ float g_v[BB * DD];
__device__ float g_o[BB * DD];

// y[b][d] = sum_k x[b][k] * W[d][k] + bias[d]
// One warp per output row d; all 4 batches accumulated simultaneously.
// x (BB*DD floats = 32KB) staged in shared memory as float4.
__device__ __forceinline__ void gemv4_body(const float* __restrict__ W,
                                           const float* __restrict__ x,
                                           const float* __restrict__ bias,
                                           float* __restrict__ y) {
    __shared__ float4 xs[BB][DD / 4];  // 32 KB
    const int tid = threadIdx.x;
    const float4* x4 = (const float4*)x;
    float4* xs_flat = (float4*)xs;
    #pragma unroll
    for (int i = tid; i < BB * DD / 4; i += 256)
        xs_flat[i] = x4[i];
    __syncthreads();

    const int warp = blockIdx.x * 8 + (tid >> 5);  // 8 warps/block, 256 blocks -> 2048 rows
    const int lane = tid & 31;
    const float4* Wrow = (const float4*)(W + (size_t)warp * DD);

    float a0 = 0.f, a1 = 0.f, a2 = 0.f, a3 = 0.f;
    #pragma unroll 4
    for (int k = lane; k < DD / 4; k += 32) {
        const float4 w  = Wrow[k];
        const float4 x0 = xs[0][k];
        const float4 x1 = xs[1][k];
        const float4 x2 = xs[2][k];
        const float4 x3 = xs[3][k];
        a0 += w.x * x0.x + w.y * x0.y + w.z * x0.z + w.w * x0.w;
        a1 += w.x * x1.x + w.y * x1.y + w.z * x1.z + w.w * x1.w;
        a2 += w.x * x2.x + w.y * x2.y + w.z * x2.z + w.w * x2.w;
        a3 += w.x * x3.x + w.y * x3.y + w.z * x3.z + w.w * x3.w;
    }
    #pragma unroll
    for (int off = 16; off > 0; off >>= 1) {
        a0 += __shfl_xor_sync(0xffffffffu, a0, off);
        a1 += __shfl_xor_sync(0xffffffffu, a1, off);
        a2 += __shfl_xor_sync(0xffffffffu, a2, off);
        a3 += __shfl_xor_sync(0xffffffffu, a3, off);
    }
    if (lane == 0) {
        const float bb = bias[warp];
        y[0 * DD + warp] = a0 + bb;
        y[1 * DD + warp] = a1 + bb;
        y[2 * DD + warp] = a2 + bb;
        y[3 * DD + warp] = a3 + bb;
    }
}

// Stage 1: g_v = condition @ Wv^T + bv
__global__ __launch_bounds__(256) void gemv_v_kernel(const float* __restrict__ cond,
                                                     const float* __restrict__ Wv,
                                                     const float* __restrict__ bv) {
    gemv4_body(Wv, cond, bv, g_v);
}

// Stage 2: g_o = g_v @ Wo^T + bo
__global__ __launch_bounds__(256) void gemv_o_kernel(const float* __restrict__ Wo,
                                                     const float* __restrict__ bo) {
    gemv4_body(Wo, g_v, bo, g_o);
}

// Stage 3: out[b][s][:] = g_o[b][:]  for all s   (pure write bandwidth)
__global__ __launch_bounds__(256) void bcast_kernel(float4* __restrict__ out) {
    const int i4 = blockIdx.x * 256 + threadIdx.x;  // over BB*SS*DD/4 = 2M float4
    const int per_b = SS * DD / 4;                  // 524288
    const int b = i4 / per_b;
    const int d4 = i4 & (DD / 4 - 1);
    out[i4] = ((const float4*)g_o)[b * (DD / 4) + d4];
}

extern "C" void kernel_launch(void* const* d_in, const int* in_sizes, int n_in,
                              void* d_out, int out_size) {
    // Input order (metadata): hidden_states, condition, Wq, bq, Wk, bk, Wv, bv, Wo, bo
    const float* cond = (const float*)d_in[1];
    const float* Wv   = (const float*)d_in[6];
    const float* bv   = (const float*)d_in[7];
    const float* Wo   = (const float*)d_in[8];
    const float* bo   = (const float*)d_in[9];
    float* out = (float*)d_out;

    gemv_v_kernel<<<DD / 8, 256>>>(cond, Wv, bv);
    gemv_o_kernel<<<DD / 8, 256>>>(Wo, bo);
    bcast_kernel<<<(BB * SS * DD / 4) / 256, 256>>>((float4*)out);
}

// round 3
// speedup vs baseline: 1.0153x; 1.0153x over previous
#include <cuda_runtime.h>
#include <cuda_bf16.h>

// Problem constants
#define BB 4
#define SS 1024
#define DD 2048

// Scratch (allocation-free rule: __device__ globals)
__device__ float g_v[BB * DD];
__device__ float g_o[BB * DD];

// y[b][d] = sum_k x[b][k] * W[d][k] + bias[d]
// One warp per output row d; 8 rows per block, 256 blocks.
// Key change vs R2: ALL 16 W-float4 loads per lane are issued up-front
// (MLP=16, front-batched) before any shared-memory reads or FMAs, so DRAM
// latency is fully overlapped even at ~15 resident warps/SM.
__device__ __forceinline__ void gemv4_body(const float* __restrict__ W,
                                           const float* __restrict__ x,
                                           const float* __restrict__ bias,
                                           float* __restrict__ y) {
    __shared__ float4 xs[BB][DD / 4];  // 32 KB
    const int tid = threadIdx.x;
    const float4* x4 = (const float4*)x;
    float4* xs_flat = (float4*)xs;
    #pragma unroll
    for (int i = tid; i < BB * DD / 4; i += 256)
        xs_flat[i] = x4[i];

    const int warp = blockIdx.x * 8 + (tid >> 5);
    const int lane = tid & 31;
    const float4* Wrow = (const float4*)(W + (size_t)warp * DD);

    // Front-batch the whole row slice: 16 independent LDG.128 per lane.
    float4 w[16];
    #pragma unroll
    for (int i = 0; i < 16; ++i)
        w[i] = Wrow[lane + i * 32];

    __syncthreads();  // xs ready (overlapped with the 16 in-flight LDGs)

    float a0 = 0.f, a1 = 0.f, a2 = 0.f, a3 = 0.f;
    #pragma unroll
    for (int i = 0; i < 16; ++i) {
        const int k = lane + i * 32;
        const float4 ww = w[i];
        const float4 x0 = xs[0][k];
        const float4 x1 = xs[1][k];
        const float4 x2 = xs[2][k];
        const float4 x3 = xs[3][k];
        a0 += ww.x * x0.x + ww.y * x0.y + ww.z * x0.z + ww.w * x0.w;
        a1 += ww.x * x1.x + ww.y * x1.y + ww.z * x1.z + ww.w * x1.w;
        a2 += ww.x * x2.x + ww.y * x2.y + ww.z * x2.z + ww.w * x2.w;
        a3 += ww.x * x3.x + ww.y * x3.y + ww.z * x3.z + ww.w * x3.w;
    }
    #pragma unroll
    for (int off = 16; off > 0; off >>= 1) {
        a0 += __shfl_xor_sync(0xffffffffu, a0, off);
        a1 += __shfl_xor_sync(0xffffffffu, a1, off);
        a2 += __shfl_xor_sync(0xffffffffu, a2, off);
        a3 += __shfl_xor_sync(0xffffffffu, a3, off);
    }
    if (lane == 0) {
        const float bb = bias[warp];
        y[0 * DD + warp] = a0 + bb;
        y[1 * DD + warp] = a1 + bb;
        y[2 * DD + warp] = a2 + bb;
        y[3 * DD + warp] = a3 + bb;
    }
}

// Stage 1: g_v = condition @ Wv^T + bv
__global__ __launch_bounds__(256) void gemv_v_kernel(const float* __restrict__ cond,
                                                     const float* __restrict__ Wv,
                                                     const float* __restrict__ bv) {
    gemv4_body(Wv, cond, bv, g_v);
}

// Stage 2: g_o = g_v @ Wo^T + bo
__global__ __launch_bounds__(256) void gemv_o_kernel(const float* __restrict__ Wo,
                                                     const float* __restrict__ bo) {
    gemv4_body(Wo, g_v, bo, g_o);
}

// Stage 3: out[b][s][:] = g_o[b][:]  for all s   (pure write bandwidth)
__global__ __launch_bounds__(256) void bcast_kernel(float4* __restrict__ out) {
    const int i4 = blockIdx.x * 256 + threadIdx.x;  // over BB*SS*DD/4 = 2M float4
    const int per_b = SS * DD / 4;                  // 524288
    const int b = i4 / per_b;
    const int d4 = i4 & (DD / 4 - 1);
    out[i4] = ((const float4*)g_o)[b * (DD / 4) + d4];
}

extern "C" void kernel_launch(void* const* d_in, const int* in_sizes, int n_in,
                              void* d_out, int out_size) {
    // Input order (metadata): hidden_states, condition, Wq, bq, Wk, bk, Wv, bv, Wo, bo
    const float* cond = (const float*)d_in[1];
    const float* Wv   = (const float*)d_in[6];
    const float* bv   = (const float*)d_in[7];
    const float* Wo   = (const float*)d_in[8];
    const float* bo   = (const float*)d_in[9];
    float* out = (float*)d_out;

    gemv_v_kernel<<<DD / 8, 256>>>(cond, Wv, bv);
    gemv_o_kernel<<<DD / 8, 256>>>(Wo, bo);
    bcast_kernel<<<(BB * SS * DD / 4) / 256, 256>>>((float4*)out);
}